// round 15
// baseline (speedup 1.0000x reference)
#include <cuda_runtime.h>
#include <cstdint>
#include <cstddef>

// ---------------------------------------------------------------------------
// Problem constants
// ---------------------------------------------------------------------------
#define B_NW   8192
#define NTOK   64
#define CDIM   256
#define NH     8
#define HD     32
#define MROWS  (B_NW * NTOK)          // 524288
#define QKV_N  768
#define SCALE  0.17677669529663687f   // 32^-0.5

// GEMM1 tiling (R8 config: BM=128, 3-stage, 1 barrier/chunk, 2 CTAs/SM)
#define BM   128
#define BN   128
#define BK   32
#define NCHUNK (CDIM / BK)            // 8
#define STAGES 3
#define PITCH (BK + 4)                // 36 floats
#define ASZ  (BM * PITCH)
#define BSZ  (BN * PITCH)
#define STG_FLOATS (ASZ + BSZ)
#define SMEM_DYN (STAGES * STG_FLOATS * 4)   // 110592 B

// Fused attention+proj smem (floats)
#define FP    260                     // att tile pitch
#define F_ATT 0                       // att[64][260] = 16640
#define F_WK  (NTOK * FP)             // work area base
#define WK_U    0                     // u[4480]: qs[64*36] | kT[32*68] -> sc[64*68]
#define WK_VS   4480                  // vs[64][36] = 2304
#define WK_SI   (4480 + 2304)         // s_inv[64]
#define WK_SIZE 9216                  // max(attn work 6848, B staging 2*4608)
#define U_KT  2304
#define FUSED_SMEM ((F_WK + WK_SIZE) * 4)    // 103424 B
#define PBSZ  (128 * PITCH)           // proj B stage: 4608 floats

// ---------------------------------------------------------------------------
// Static device scratch
// ---------------------------------------------------------------------------
__device__ float g_qkv[(size_t)MROWS * QKV_N];        // QKV output [M, 768]
__device__ float g_wr [QKV_N * CDIM + CDIM * CDIM];   // rounded qkv_w | proj_w
__device__ float g_bias[NH * NTOK * NTOK];            // precomputed rel-pos bias

// ---------------------------------------------------------------------------
// Helpers
// ---------------------------------------------------------------------------
__device__ __forceinline__ uint32_t s2u(const void* p) {
    uint32_t a;
    asm("{ .reg .u64 t; cvta.to.shared.u64 t, %1; cvt.u32.u64 %0, t; }"
        : "=r"(a) : "l"(p));
    return a;
}

__device__ __forceinline__ float rtf(float x) {
    float y;
    asm("cvt.rna.tf32.f32 %0, %1;" : "=f"(y) : "f"(x));
    return y;
}

__device__ __forceinline__ void rtf_r(uint32_t& u) {
    asm("cvt.rna.tf32.f32 %0, %0;" : "+r"(u));
}

__device__ __forceinline__ void cp16(uint32_t dst, const void* src) {
    asm volatile("cp.async.cg.shared.global [%0], [%1], 16;"
                 :: "r"(dst), "l"(src) : "memory");
}

__device__ __forceinline__ void mma8(float* c, const uint32_t* a, const uint32_t* b) {
    asm volatile(
        "mma.sync.aligned.m16n8k8.row.col.f32.tf32.tf32.f32 "
        "{%0,%1,%2,%3}, {%4,%5,%6,%7}, {%8,%9}, {%0,%1,%2,%3};"
        : "+f"(c[0]), "+f"(c[1]), "+f"(c[2]), "+f"(c[3])
        : "r"(a[0]), "r"(a[1]), "r"(a[2]), "r"(a[3]), "r"(b[0]), "r"(b[1]));
}

__device__ __forceinline__ void ldsm4(uint32_t* r, uint32_t addr) {
    asm volatile("ldmatrix.sync.aligned.m8n8.x4.shared.b16 {%0,%1,%2,%3}, [%4];"
                 : "=r"(r[0]), "=r"(r[1]), "=r"(r[2]), "=r"(r[3]) : "r"(addr));
}

// f32x2 packed FMA helpers
__device__ __forceinline__ unsigned long long pack2(float a) {
    unsigned long long r;
    asm("mov.b64 %0, {%1, %1};" : "=l"(r) : "f"(a));
    return r;
}
__device__ __forceinline__ void ffma2(unsigned long long& acc,
                                      unsigned long long a,
                                      unsigned long long b) {
    asm("fma.rn.f32x2 %0, %1, %2, %0;" : "+l"(acc) : "l"(a), "l"(b));
}
__device__ __forceinline__ float2 unpack2(unsigned long long v) {
    float2 r;
    asm("mov.b64 {%0, %1}, %2;" : "=f"(r.x), "=f"(r.y) : "l"(v));
    return r;
}

// Fast exp on the FMA pipe (no MUFU). Valid post max-subtraction (x <= 0).
__device__ __forceinline__ float fexp(float x) {
    float t = fmaxf(x * 1.4426950408889634f, -126.0f);
    float j = rintf(t);
    float f = t - j;
    float p =               1.33335581e-3f;
    p = __fmaf_rn(p, f, 9.61812911e-3f);
    p = __fmaf_rn(p, f, 5.55041087e-2f);
    p = __fmaf_rn(p, f, 2.40226507e-1f);
    p = __fmaf_rn(p, f, 6.93147181e-1f);
    p = __fmaf_rn(p, f, 1.0f);
    int ji = (int)j;
    return p * __int_as_float((ji + 127) << 23);
}

// ---------------------------------------------------------------------------
// tf32 rounding pass (weights only — tiny)
// ---------------------------------------------------------------------------
__global__ __launch_bounds__(256)
void round_tf32_kernel(const float4* __restrict__ s, float4* __restrict__ d, int n4) {
    int i = blockIdx.x * 256 + threadIdx.x;
    if (i < n4) {
        float4 v = s[i];
        v.x = rtf(v.x); v.y = rtf(v.y); v.z = rtf(v.z); v.w = rtf(v.w);
        d[i] = v;
    }
}

// ---------------------------------------------------------------------------
// Precompute bias matrix per head
// ---------------------------------------------------------------------------
__global__ __launch_bounds__(256)
void bias_kernel(const float* __restrict__ table, const int* __restrict__ rpi,
                 float* __restrict__ gb) {
    int h = blockIdx.y;
    int i = blockIdx.x * 256 + threadIdx.x;
    gb[h * 4096 + i] = table[rpi[i] * NH + h];
}

// ---------------------------------------------------------------------------
// tf32 mma.sync GEMM (NT), R8 config: C = A @ W^T + bias.
// BM=128, 3-stage cp.async, one __syncthreads per K-chunk, 2 CTAs/SM.
// ---------------------------------------------------------------------------
template<bool CVT_A>
__global__ __launch_bounds__(256, 2)
void gemm_mma_kernel(const float* __restrict__ A,
                     const float* __restrict__ W,
                     const float* __restrict__ bias,
                     float* __restrict__ C,
                     int Ncols)
{
    extern __shared__ float sm[];

    const int t      = threadIdx.x;
    const int w      = t >> 5;
    const int lane   = t & 31;
    const int g      = lane >> 2;
    const int tg     = lane & 3;
    const int warp_m = w >> 2;
    const int warp_n = w & 3;
    const size_t row0 = (size_t)blockIdx.y * BM;
    const int    col0 = blockIdx.x * BN;

    const int lrow8 = lane & 7;
    const int lsel  = (lane >> 3) & 1;
    const int lhalf = lane >> 4;
    const uint32_t aoff = (uint32_t)((warp_m * 64 + lsel * 8 + lrow8) * PITCH + lhalf * 4) * 4;
    const uint32_t boff = (uint32_t)((warp_n * 32 + lhalf * 8 + lrow8) * PITCH + lsel * 4) * 4;

    const uint32_t smb = s2u(sm);

    auto load_chunk = [&](int kc, int stg) {
        const uint32_t aB = smb + (uint32_t)(stg * STG_FLOATS) * 4;
        const uint32_t bB = aB + (uint32_t)ASZ * 4;
#pragma unroll
        for (int i = 0; i < 4; i++) {
            int u = t + 256 * i;
            int r = u >> 3, q = u & 7;
            cp16(aB + (uint32_t)(r * PITCH + q * 4) * 4,
                 A + (row0 + r) * CDIM + kc * BK + q * 4);
        }
#pragma unroll
        for (int i = 0; i < 4; i++) {
            int u = t + 256 * i;
            int r = u >> 3, q = u & 7;
            cp16(bB + (uint32_t)(r * PITCH + q * 4) * 4,
                 W + (size_t)(col0 + r) * CDIM + kc * BK + q * 4);
        }
        asm volatile("cp.async.commit_group;" ::: "memory");
    };

    float acc[4][4][4];
#pragma unroll
    for (int mi = 0; mi < 4; mi++)
#pragma unroll
        for (int ni = 0; ni < 4; ni++)
#pragma unroll
            for (int j = 0; j < 4; j++) acc[mi][ni][j] = 0.f;

    load_chunk(0, 0);
    load_chunk(1, 1);

#pragma unroll
    for (int c = 0; c < NCHUNK; c++) {
        const int stg = c % STAGES;
        if (c < NCHUNK - 1) asm volatile("cp.async.wait_group 1;" ::: "memory");
        else                asm volatile("cp.async.wait_group 0;" ::: "memory");
        __syncthreads();
        if (c + 2 < NCHUNK) load_chunk(c + 2, (c + 2) % STAGES);

        const uint32_t aB = smb + (uint32_t)(stg * STG_FLOATS) * 4 + aoff;
        const uint32_t bB = smb + (uint32_t)(stg * STG_FLOATS + ASZ) * 4 + boff;

#pragma unroll
        for (int ks = 0; ks < 4; ks++) {
            const uint32_t kb = (uint32_t)(ks * 8) * 4;
            uint32_t af[4][4], bf[4][2];
#pragma unroll
            for (int mi = 0; mi < 4; mi++) {
                ldsm4(af[mi], aB + (uint32_t)(mi * 16 * PITCH) * 4 + kb);
                if (CVT_A) {
                    rtf_r(af[mi][0]); rtf_r(af[mi][1]);
                    rtf_r(af[mi][2]); rtf_r(af[mi][3]);
                }
            }
            {
                uint32_t r[4];
                ldsm4(r, bB + kb);
                bf[0][0] = r[0]; bf[0][1] = r[1]; bf[1][0] = r[2]; bf[1][1] = r[3];
                ldsm4(r, bB + (uint32_t)(16 * PITCH) * 4 + kb);
                bf[2][0] = r[0]; bf[2][1] = r[1]; bf[3][0] = r[2]; bf[3][1] = r[3];
            }
#pragma unroll
            for (int mi = 0; mi < 4; mi++)
#pragma unroll
                for (int ni = 0; ni < 4; ni++)
                    mma8(acc[mi][ni], af[mi], bf[ni]);
        }
    }

#pragma unroll
    for (int ni = 0; ni < 4; ni++) {
        const int col = col0 + warp_n * 32 + ni * 8 + 2 * tg;
        const float bx = __ldg(&bias[col]);
        const float by = __ldg(&bias[col + 1]);
#pragma unroll
        for (int mi = 0; mi < 4; mi++) {
            const size_t rlo = row0 + warp_m * 64 + mi * 16 + g;
            float2 v0 = { acc[mi][ni][0] + bx, acc[mi][ni][1] + by };
            float2 v1 = { acc[mi][ni][2] + bx, acc[mi][ni][3] + by };
            *(float2*)(C + rlo * (size_t)Ncols + col)       = v0;
            *(float2*)(C + (rlo + 8) * (size_t)Ncols + col) = v1;
        }
    }
}

// ---------------------------------------------------------------------------
// Fused window attention + output projection. One block per WINDOW (8192).
// Phase 1: loop 8 heads, f32x2 attention (R11 code), results -> att smem tile.
// Phase 2: proj GEMM 64x256x256 via mma from smem, proj_w streamed by cp.async.
// ---------------------------------------------------------------------------
__global__ __launch_bounds__(256, 2)
void attn_proj_kernel(const float* __restrict__ qkv,
                      const float* __restrict__ gbias,
                      const float* __restrict__ wproj,   // pre-rounded [256,256]
                      const float* __restrict__ proj_b,
                      float* __restrict__ out)
{
    extern __shared__ float sb[];
    float* att  = sb + F_ATT;            // [64][260]
    float* wk   = sb + F_WK;             // work area (attn | B staging)
    float* u    = wk + WK_U;             // qs[64*36] | kT[32*68] -> sc[64*68]
    float* vs   = wk + WK_VS;            // [64][36]
    float* s_iv = wk + WK_SI;            // [64]

    const int b = blockIdx.x;
    const int t = threadIdx.x;

    const float* base = qkv + (size_t)b * NTOK * QKV_N;

    // ================= Phase 1: attention, 8 heads =================
    for (int h = 0; h < NH; h++) {
        const float* biash = gbias + h * NTOK * NTOK;

        // ---- load q (scaled), kT (transposed), v for head h ----
        for (int i = t; i < 3 * 512; i += 256) {
            int which = i >> 9;
            int rem   = i & 511;
            int r     = rem >> 3;
            int f     = rem & 7;
            float4 v4 = *(const float4*)(base + (size_t)r * QKV_N + which * CDIM + h * HD + f * 4);
            if (which == 0) {
                v4.x *= SCALE; v4.y *= SCALE; v4.z *= SCALE; v4.w *= SCALE;
                *(float4*)&u[r * 36 + f * 4] = v4;
            } else if (which == 1) {
                u[U_KT + (f * 4 + 0) * 68 + r] = v4.x;
                u[U_KT + (f * 4 + 1) * 68 + r] = v4.y;
                u[U_KT + (f * 4 + 2) * 68 + r] = v4.z;
                u[U_KT + (f * 4 + 3) * 68 + r] = v4.w;
            } else {
                *(float4*)&vs[r * 36 + f * 4] = v4;
            }
        }
        __syncthreads();

        // ---- scores: 16x16 grid, 4x4 per thread, f32x2; keep in regs ----
        float sreg[4][4];
        {
            const int ti = t >> 4;
            const int tj = t & 15;
            const int r0 = ti * 4;
            const int m0 = tj * 4;
            unsigned long long accp[4][2];
#pragma unroll
            for (int i = 0; i < 4; i++) { accp[i][0] = 0ULL; accp[i][1] = 0ULL; }

#pragma unroll
            for (int dc = 0; dc < 8; dc++) {
                float4 qv[4];
                ulonglong2 kvp[4];
#pragma unroll
                for (int i = 0; i < 4; i++)
                    qv[i] = *(const float4*)&u[(r0 + i) * 36 + dc * 4];
#pragma unroll
                for (int s = 0; s < 4; s++)
                    kvp[s] = *(const ulonglong2*)&u[U_KT + (dc * 4 + s) * 68 + m0];
#pragma unroll
                for (int i = 0; i < 4; i++) {
                    unsigned long long q0 = pack2(qv[i].x);
                    unsigned long long q1 = pack2(qv[i].y);
                    unsigned long long q2 = pack2(qv[i].z);
                    unsigned long long q3 = pack2(qv[i].w);
                    ffma2(accp[i][0], q0, kvp[0].x); ffma2(accp[i][1], q0, kvp[0].y);
                    ffma2(accp[i][0], q1, kvp[1].x); ffma2(accp[i][1], q1, kvp[1].y);
                    ffma2(accp[i][0], q2, kvp[2].x); ffma2(accp[i][1], q2, kvp[2].y);
                    ffma2(accp[i][0], q3, kvp[3].x); ffma2(accp[i][1], q3, kvp[3].y);
                }
            }
#pragma unroll
            for (int i = 0; i < 4; i++) {
                float2 a0 = unpack2(accp[i][0]);
                float2 a1 = unpack2(accp[i][1]);
                float4 bv = *(const float4*)(biash + (r0 + i) * NTOK + m0);
                sreg[i][0] = a0.x + bv.x;
                sreg[i][1] = a0.y + bv.y;
                sreg[i][2] = a1.x + bv.z;
                sreg[i][3] = a1.y + bv.w;
            }
        }
        __syncthreads();   // reads of qs/kT done; u may be overwritten

        {
            const int ti = t >> 4;
            const int tj = t & 15;
            const int r0 = ti * 4;
            const int m0 = tj * 4;
#pragma unroll
            for (int i = 0; i < 4; i++) {
                float4 o = { sreg[i][0], sreg[i][1], sreg[i][2], sreg[i][3] };
                *(float4*)&u[(r0 + i) * 68 + m0] = o;
            }
        }
        __syncthreads();

        // ---- softmax: 4 threads per row ----
        {
            const int r   = t >> 2;
            const int seg = (t & 3) * 16;
            float* SC = &u[r * 68];
            float4 v0 = *(const float4*)&SC[seg];
            float4 v1 = *(const float4*)&SC[seg + 4];
            float4 v2 = *(const float4*)&SC[seg + 8];
            float4 v3 = *(const float4*)&SC[seg + 12];
            float mx = fmaxf(fmaxf(fmaxf(v0.x, v0.y), fmaxf(v0.z, v0.w)),
                       fmaxf(fmaxf(fmaxf(v1.x, v1.y), fmaxf(v1.z, v1.w)),
                       fmaxf(fmaxf(fmaxf(v2.x, v2.y), fmaxf(v2.z, v2.w)),
                             fmaxf(fmaxf(v3.x, v3.y), fmaxf(v3.z, v3.w)))));
            mx = fmaxf(mx, __shfl_xor_sync(0xffffffffu, mx, 1, 4));
            mx = fmaxf(mx, __shfl_xor_sync(0xffffffffu, mx, 2, 4));

            v0.x = fexp(v0.x - mx); v0.y = fexp(v0.y - mx);
            v0.z = fexp(v0.z - mx); v0.w = fexp(v0.w - mx);
            v1.x = fexp(v1.x - mx); v1.y = fexp(v1.y - mx);
            v1.z = fexp(v1.z - mx); v1.w = fexp(v1.w - mx);
            v2.x = fexp(v2.x - mx); v2.y = fexp(v2.y - mx);
            v2.z = fexp(v2.z - mx); v2.w = fexp(v2.w - mx);
            v3.x = fexp(v3.x - mx); v3.y = fexp(v3.y - mx);
            v3.z = fexp(v3.z - mx); v3.w = fexp(v3.w - mx);

            float sum = (v0.x + v0.y + v0.z + v0.w) + (v1.x + v1.y + v1.z + v1.w)
                      + (v2.x + v2.y + v2.z + v2.w) + (v3.x + v3.y + v3.z + v3.w);
            sum += __shfl_xor_sync(0xffffffffu, sum, 1, 4);
            sum += __shfl_xor_sync(0xffffffffu, sum, 2, 4);

            *(float4*)&SC[seg]      = v0;
            *(float4*)&SC[seg + 4]  = v1;
            *(float4*)&SC[seg + 8]  = v2;
            *(float4*)&SC[seg + 12] = v3;
            if ((t & 3) == 0) s_iv[r] = 1.f / sum;
        }
        __syncthreads();

        // ---- out: 2 rows x 4 d per thread -> att smem tile (tf32-rounded) ----
        {
            const int p  = t >> 3;
            const int dq = t & 7;
            const int r0 = p * 2;
            unsigned long long o0[2] = { 0ULL, 0ULL };
            unsigned long long o1[2] = { 0ULL, 0ULL };
#pragma unroll
            for (int mc = 0; mc < 16; mc++) {
                float4 p0 = *(const float4*)&u[r0 * 68 + mc * 4];
                float4 p1 = *(const float4*)&u[(r0 + 1) * 68 + mc * 4];
                ulonglong2 vv[4];
#pragma unroll
                for (int s = 0; s < 4; s++)
                    vv[s] = *(const ulonglong2*)&vs[(mc * 4 + s) * 36 + dq * 4];
                {
                    unsigned long long a;
                    a = pack2(p0.x); ffma2(o0[0], a, vv[0].x); ffma2(o0[1], a, vv[0].y);
                    a = pack2(p0.y); ffma2(o0[0], a, vv[1].x); ffma2(o0[1], a, vv[1].y);
                    a = pack2(p0.z); ffma2(o0[0], a, vv[2].x); ffma2(o0[1], a, vv[2].y);
                    a = pack2(p0.w); ffma2(o0[0], a, vv[3].x); ffma2(o0[1], a, vv[3].y);
                    a = pack2(p1.x); ffma2(o1[0], a, vv[0].x); ffma2(o1[1], a, vv[0].y);
                    a = pack2(p1.y); ffma2(o1[0], a, vv[1].x); ffma2(o1[1], a, vv[1].y);
                    a = pack2(p1.z); ffma2(o1[0], a, vv[2].x); ffma2(o1[1], a, vv[2].y);
                    a = pack2(p1.w); ffma2(o1[0], a, vv[3].x); ffma2(o1[1], a, vv[3].y);
                }
            }
            const float i0 = s_iv[r0];
            const float i1 = s_iv[r0 + 1];
            float2 a0 = unpack2(o0[0]), a1 = unpack2(o0[1]);
            float2 b0 = unpack2(o1[0]), b1 = unpack2(o1[1]);
            float4 w0 = { rtf(a0.x * i0), rtf(a0.y * i0), rtf(a1.x * i0), rtf(a1.y * i0) };
            float4 w1 = { rtf(b0.x * i1), rtf(b0.y * i1), rtf(b1.x * i1), rtf(b1.y * i1) };
            *(float4*)&att[r0 * FP + h * HD + dq * 4]       = w0;
            *(float4*)&att[(r0 + 1) * FP + h * HD + dq * 4] = w1;
        }
        __syncthreads();   // u/vs free for next head; att writes visible later
    }

    // ================= Phase 2: proj GEMM 64x256x256 =================
    {
        const int w      = t >> 5;
        const int lane   = t & 31;
        const int g      = lane >> 2;
        const int tg     = lane & 3;
        const int warp_m = w >> 2;        // 0..1
        const int warp_n = w & 3;         // 0..3
        const int lrow8 = lane & 7;
        const int lsel  = (lane >> 3) & 1;
        const int lhalf = lane >> 4;

        const uint32_t attB = s2u(att) +
            (uint32_t)((warp_m * 32 + lsel * 8 + lrow8) * FP + lhalf * 4) * 4;
        const uint32_t stgB = s2u(wk);
        const uint32_t boff =
            (uint32_t)((warp_n * 32 + lhalf * 8 + lrow8) * PITCH + lsel * 4) * 4;

        auto load_b = [&](int col0, int kc, int stg) {
            const uint32_t bB = stgB + (uint32_t)(stg * PBSZ) * 4;
#pragma unroll
            for (int i = 0; i < 4; i++) {      // 128 rows x 8 x 16B
                int uu = t + 256 * i;
                int r = uu >> 3, q = uu & 7;
                cp16(bB + (uint32_t)(r * PITCH + q * 4) * 4,
                     wproj + (size_t)(col0 + r) * CDIM + kc * BK + q * 4);
            }
            asm volatile("cp.async.commit_group;" ::: "memory");
        };

#pragma unroll
        for (int nh = 0; nh < 2; nh++) {
            const int col0 = nh * 128;
            float acc[2][4][4];
#pragma unroll
            for (int mi = 0; mi < 2; mi++)
#pragma unroll
                for (int ni = 0; ni < 4; ni++)
#pragma unroll
                    for (int j = 0; j < 4; j++) acc[mi][ni][j] = 0.f;

            load_b(col0, 0, 0);

#pragma unroll
            for (int c = 0; c < NCHUNK; c++) {
                const int stg = c & 1;
                if (c + 1 < NCHUNK) {
                    load_b(col0, c + 1, (c + 1) & 1);
                    asm volatile("cp.async.wait_group 1;" ::: "memory");
                } else {
                    asm volatile("cp.async.wait_group 0;" ::: "memory");
                }
                __syncthreads();

                const uint32_t aB = attB + (uint32_t)(c * BK) * 4;
                const uint32_t bB = stgB + (uint32_t)(stg * PBSZ) * 4 + boff;

#pragma unroll
                for (int ks = 0; ks < 4; ks++) {
                    const uint32_t kb = (uint32_t)(ks * 8) * 4;
                    uint32_t af[2][4], bf[4][2];
#pragma unroll
                    for (int mi = 0; mi < 2; mi++)
                        ldsm4(af[mi], aB + (uint32_t)(mi * 16 * FP) * 4 + kb);
                    {
                        uint32_t r[4];
                        ldsm4(r, bB + kb);
                        bf[0][0] = r[0]; bf[0][1] = r[1]; bf[1][0] = r[2]; bf[1][1] = r[3];
                        ldsm4(r, bB + (uint32_t)(16 * PITCH) * 4 + kb);
                        bf[2][0] = r[0]; bf[2][1] = r[1]; bf[3][0] = r[2]; bf[3][1] = r[3];
                    }
#pragma unroll
                    for (int mi = 0; mi < 2; mi++)
#pragma unroll
                        for (int ni = 0; ni < 4; ni++)
                            mma8(acc[mi][ni], af[mi], bf[ni]);
                }
                __syncthreads();
            }

#pragma unroll
            for (int ni = 0; ni < 4; ni++) {
                const int col = col0 + warp_n * 32 + ni * 8 + 2 * tg;
                const float bx = __ldg(&proj_b[col]);
                const float by = __ldg(&proj_b[col + 1]);
#pragma unroll
                for (int mi = 0; mi < 2; mi++) {
                    const int rlo = warp_m * 32 + mi * 16 + g;
                    const size_t row = (size_t)b * NTOK + rlo;
                    float2 v0 = { acc[mi][ni][0] + bx, acc[mi][ni][1] + by };
                    float2 v1 = { acc[mi][ni][2] + bx, acc[mi][ni][3] + by };
                    *(float2*)(out + row * CDIM + col)       = v0;
                    *(float2*)(out + (row + 8) * CDIM + col) = v1;
                }
            }
        }
    }
}

// ---------------------------------------------------------------------------
// Launch
// ---------------------------------------------------------------------------
extern "C" void kernel_launch(void* const* d_in, const int* in_sizes, int n_in,
                              void* d_out, int out_size)
{
    const float* x       = (const float*)d_in[0];
    const float* qkv_w   = (const float*)d_in[1];
    const float* qkv_b   = (const float*)d_in[2];
    const float* proj_w  = (const float*)d_in[3];
    const float* proj_b  = (const float*)d_in[4];
    const float* table   = (const float*)d_in[5];
    const int*   rpi     = (const int*)  d_in[6];
    float*       out     = (float*)d_out;

    float *qkv_s, *wr_s, *bias_s;
    cudaGetSymbolAddress((void**)&qkv_s,  g_qkv);
    cudaGetSymbolAddress((void**)&wr_s,   g_wr);
    cudaGetSymbolAddress((void**)&bias_s, g_bias);
    float* wqkv_r  = wr_s;
    float* wproj_r = wr_s + QKV_N * CDIM;

    cudaFuncSetAttribute(gemm_mma_kernel<true>,
                         cudaFuncAttributeMaxDynamicSharedMemorySize, SMEM_DYN);
    cudaFuncSetAttribute(attn_proj_kernel,
                         cudaFuncAttributeMaxDynamicSharedMemorySize, FUSED_SMEM);

    // 0) Precompute bias matrices + RN-round weights (tiny)
    bias_kernel<<<dim3(16, NH), 256>>>(table, rpi, bias_s);
    {
        int n4w1 = QKV_N * CDIM / 4;
        round_tf32_kernel<<<(n4w1 + 255) / 256, 256>>>((const float4*)qkv_w, (float4*)wqkv_r, n4w1);
        int n4w2 = CDIM * CDIM / 4;
        round_tf32_kernel<<<(n4w2 + 255) / 256, 256>>>((const float4*)proj_w, (float4*)wproj_r, n4w2);
    }

    // 1) QKV projection: A = raw x, rounded in-register (CVT_A=true)
    gemm_mma_kernel<true><<<dim3(QKV_N / BN, MROWS / BM), 256, SMEM_DYN>>>(
        x, wqkv_r, qkv_b, qkv_s, QKV_N);

    // 2) Fused window attention + output projection
    attn_proj_kernel<<<B_NW, 256, FUSED_SMEM>>>(qkv_s, bias_s, wproj_r, proj_b, out);
}

// round 16
// speedup vs baseline: 1.4079x; 1.4079x over previous
#include <cuda_runtime.h>
#include <cstdint>
#include <cstddef>

// ---------------------------------------------------------------------------
// Problem constants
// ---------------------------------------------------------------------------
#define B_NW   8192
#define NTOK   64
#define CDIM   256
#define NH     8
#define HD     32
#define MROWS  (B_NW * NTOK)          // 524288
#define QKV_N  768
#define SCALE  0.17677669529663687f   // 32^-0.5

// GEMM tiling (R8 config: BM=128, 3-stage, 1 barrier/chunk, 2 CTAs/SM)
#define BM   128
#define BN   128
#define BK   32
#define NCHUNK (CDIM / BK)            // 8
#define STAGES 3
#define PITCH (BK + 4)                // 36 floats
#define ASZ  (BM * PITCH)
#define BSZ  (BN * PITCH)
#define STG_FLOATS (ASZ + BSZ)
#define SMEM_DYN (STAGES * STG_FLOATS * 4)   // 110592 B

// Attention smem layout (floats): q/k K-major pitch 36, vT/sc pitch 68
#define AP   36
#define SP   68
#define O_Q  0
#define O_K  (O_Q + NTOK * AP)        // 2304
#define O_V  (O_K + NTOK * AP)        // 4608  vT[32][68]
#define O_S  (O_V + HD * SP)          // 6784  sc[64][68]
#define O_I  (O_S + NTOK * SP)        // 11136 inv[64]
#define ATT_FLOATS (O_I + NTOK)       // 11200 -> 44800 B

// ---------------------------------------------------------------------------
// Static device scratch
// ---------------------------------------------------------------------------
__device__ float g_qkv[(size_t)MROWS * QKV_N];        // QKV output [M, 768]
__device__ float g_att[(size_t)MROWS * CDIM];         // attention out (tf32-rounded)
__device__ float g_wr [QKV_N * CDIM + CDIM * CDIM];   // rounded qkv_w | proj_w
__device__ float g_bias[NH * NTOK * NTOK];            // precomputed rel-pos bias

// ---------------------------------------------------------------------------
// Helpers
// ---------------------------------------------------------------------------
__device__ __forceinline__ uint32_t s2u(const void* p) {
    uint32_t a;
    asm("{ .reg .u64 t; cvta.to.shared.u64 t, %1; cvt.u32.u64 %0, t; }"
        : "=r"(a) : "l"(p));
    return a;
}

__device__ __forceinline__ float rtf(float x) {
    float y;
    asm("cvt.rna.tf32.f32 %0, %1;" : "=f"(y) : "f"(x));
    return y;
}

__device__ __forceinline__ void rtf_r(uint32_t& u) {
    asm("cvt.rna.tf32.f32 %0, %0;" : "+r"(u));
}

__device__ __forceinline__ void cp16(uint32_t dst, const void* src) {
    asm volatile("cp.async.cg.shared.global [%0], [%1], 16;"
                 :: "r"(dst), "l"(src) : "memory");
}

__device__ __forceinline__ void mma8(float* c, const uint32_t* a, const uint32_t* b) {
    asm volatile(
        "mma.sync.aligned.m16n8k8.row.col.f32.tf32.tf32.f32 "
        "{%0,%1,%2,%3}, {%4,%5,%6,%7}, {%8,%9}, {%0,%1,%2,%3};"
        : "+f"(c[0]), "+f"(c[1]), "+f"(c[2]), "+f"(c[3])
        : "r"(a[0]), "r"(a[1]), "r"(a[2]), "r"(a[3]), "r"(b[0]), "r"(b[1]));
}

__device__ __forceinline__ void ldsm4(uint32_t* r, uint32_t addr) {
    asm volatile("ldmatrix.sync.aligned.m8n8.x4.shared.b16 {%0,%1,%2,%3}, [%4];"
                 : "=r"(r[0]), "=r"(r[1]), "=r"(r[2]), "=r"(r[3]) : "r"(addr));
}

// Fast exp on the FMA pipe (no MUFU). Valid post max-subtraction (x <= 0).
__device__ __forceinline__ float fexp(float x) {
    float t = fmaxf(x * 1.4426950408889634f, -126.0f);
    float j = rintf(t);
    float f = t - j;
    float p =               1.33335581e-3f;
    p = __fmaf_rn(p, f, 9.61812911e-3f);
    p = __fmaf_rn(p, f, 5.55041087e-2f);
    p = __fmaf_rn(p, f, 2.40226507e-1f);
    p = __fmaf_rn(p, f, 6.93147181e-1f);
    p = __fmaf_rn(p, f, 1.0f);
    int ji = (int)j;
    return p * __int_as_float((ji + 127) << 23);
}

// ---------------------------------------------------------------------------
// tf32 rounding pass (weights only — tiny)
// ---------------------------------------------------------------------------
__global__ __launch_bounds__(256)
void round_tf32_kernel(const float4* __restrict__ s, float4* __restrict__ d, int n4) {
    int i = blockIdx.x * 256 + threadIdx.x;
    if (i < n4) {
        float4 v = s[i];
        v.x = rtf(v.x); v.y = rtf(v.y); v.z = rtf(v.z); v.w = rtf(v.w);
        d[i] = v;
    }
}

// ---------------------------------------------------------------------------
// Precompute bias matrix per head
// ---------------------------------------------------------------------------
__global__ __launch_bounds__(256)
void bias_kernel(const float* __restrict__ table, const int* __restrict__ rpi,
                 float* __restrict__ gb) {
    int h = blockIdx.y;
    int i = blockIdx.x * 256 + threadIdx.x;
    gb[h * 4096 + i] = table[rpi[i] * NH + h];
}

// ---------------------------------------------------------------------------
// tf32 mma.sync GEMM (NT), R8 config: C = A @ W^T + bias.
// ---------------------------------------------------------------------------
template<bool CVT_A>
__global__ __launch_bounds__(256, 2)
void gemm_mma_kernel(const float* __restrict__ A,
                     const float* __restrict__ W,
                     const float* __restrict__ bias,
                     float* __restrict__ C,
                     int Ncols)
{
    extern __shared__ float sm[];

    const int t      = threadIdx.x;
    const int w      = t >> 5;
    const int lane   = t & 31;
    const int g      = lane >> 2;
    const int tg     = lane & 3;
    const int warp_m = w >> 2;
    const int warp_n = w & 3;
    const size_t row0 = (size_t)blockIdx.y * BM;
    const int    col0 = blockIdx.x * BN;

    const int lrow8 = lane & 7;
    const int lsel  = (lane >> 3) & 1;
    const int lhalf = lane >> 4;
    const uint32_t aoff = (uint32_t)((warp_m * 64 + lsel * 8 + lrow8) * PITCH + lhalf * 4) * 4;
    const uint32_t boff = (uint32_t)((warp_n * 32 + lhalf * 8 + lrow8) * PITCH + lsel * 4) * 4;

    const uint32_t smb = s2u(sm);

    auto load_chunk = [&](int kc, int stg) {
        const uint32_t aB = smb + (uint32_t)(stg * STG_FLOATS) * 4;
        const uint32_t bB = aB + (uint32_t)ASZ * 4;
#pragma unroll
        for (int i = 0; i < 4; i++) {
            int u = t + 256 * i;
            int r = u >> 3, q = u & 7;
            cp16(aB + (uint32_t)(r * PITCH + q * 4) * 4,
                 A + (row0 + r) * CDIM + kc * BK + q * 4);
        }
#pragma unroll
        for (int i = 0; i < 4; i++) {
            int u = t + 256 * i;
            int r = u >> 3, q = u & 7;
            cp16(bB + (uint32_t)(r * PITCH + q * 4) * 4,
                 W + (size_t)(col0 + r) * CDIM + kc * BK + q * 4);
        }
        asm volatile("cp.async.commit_group;" ::: "memory");
    };

    float acc[4][4][4];
#pragma unroll
    for (int mi = 0; mi < 4; mi++)
#pragma unroll
        for (int ni = 0; ni < 4; ni++)
#pragma unroll
            for (int j = 0; j < 4; j++) acc[mi][ni][j] = 0.f;

    load_chunk(0, 0);
    load_chunk(1, 1);

#pragma unroll
    for (int c = 0; c < NCHUNK; c++) {
        const int stg = c % STAGES;
        if (c < NCHUNK - 1) asm volatile("cp.async.wait_group 1;" ::: "memory");
        else                asm volatile("cp.async.wait_group 0;" ::: "memory");
        __syncthreads();
        if (c + 2 < NCHUNK) load_chunk(c + 2, (c + 2) % STAGES);

        const uint32_t aB = smb + (uint32_t)(stg * STG_FLOATS) * 4 + aoff;
        const uint32_t bB = smb + (uint32_t)(stg * STG_FLOATS + ASZ) * 4 + boff;

#pragma unroll
        for (int ks = 0; ks < 4; ks++) {
            const uint32_t kb = (uint32_t)(ks * 8) * 4;
            uint32_t af[4][4], bf[4][2];
#pragma unroll
            for (int mi = 0; mi < 4; mi++) {
                ldsm4(af[mi], aB + (uint32_t)(mi * 16 * PITCH) * 4 + kb);
                if (CVT_A) {
                    rtf_r(af[mi][0]); rtf_r(af[mi][1]);
                    rtf_r(af[mi][2]); rtf_r(af[mi][3]);
                }
            }
            {
                uint32_t r[4];
                ldsm4(r, bB + kb);
                bf[0][0] = r[0]; bf[0][1] = r[1]; bf[1][0] = r[2]; bf[1][1] = r[3];
                ldsm4(r, bB + (uint32_t)(16 * PITCH) * 4 + kb);
                bf[2][0] = r[0]; bf[2][1] = r[1]; bf[3][0] = r[2]; bf[3][1] = r[3];
            }
#pragma unroll
            for (int mi = 0; mi < 4; mi++)
#pragma unroll
                for (int ni = 0; ni < 4; ni++)
                    mma8(acc[mi][ni], af[mi], bf[ni]);
        }
    }

#pragma unroll
    for (int ni = 0; ni < 4; ni++) {
        const int col = col0 + warp_n * 32 + ni * 8 + 2 * tg;
        const float bx = __ldg(&bias[col]);
        const float by = __ldg(&bias[col + 1]);
#pragma unroll
        for (int mi = 0; mi < 4; mi++) {
            const size_t rlo = row0 + warp_m * 64 + mi * 16 + g;
            float2 v0 = { acc[mi][ni][0] + bx, acc[mi][ni][1] + by };
            float2 v1 = { acc[mi][ni][2] + bx, acc[mi][ni][3] + by };
            *(float2*)(C + rlo * (size_t)Ncols + col)       = v0;
            *(float2*)(C + (rlo + 8) * (size_t)Ncols + col) = v1;
        }
    }
}

// ---------------------------------------------------------------------------
// Window attention via tensor cores, 1-term RN-tf32 (layouts validated in R9).
// One block per (window b, head h), 256 threads (8 warps).
//   QK^T: warps (wm 0-3: 16-row stripe) x (wn 0-1: 32-col half)
//   softmax: 4 threads/row, FMA-pipe exp; emits RN-rounded unnormalized p
//   P*V:  warps (wm stripe) x (wn 0-1: 16-d half)
// ---------------------------------------------------------------------------
__global__ __launch_bounds__(256)
void attn_kernel(const float* __restrict__ qkv,
                 const float* __restrict__ gbias,
                 float* __restrict__ out)
{
    __shared__ float sb[ATT_FLOATS];
    const uint32_t smb = s2u(sb);

    const int b = blockIdx.x;
    const int h = blockIdx.y;
    const int t = threadIdx.x;
    const int w    = t >> 5;
    const int lane = t & 31;
    const int g    = lane >> 2;
    const int tg   = lane & 3;
    const int wm   = w & 3;
    const int wn   = w >> 2;
    const int lrow8 = lane & 7;
    const int lsel  = (lane >> 3) & 1;
    const int lhalf = lane >> 4;

    const float* base  = qkv + (size_t)b * NTOK * QKV_N;
    const float* biash = gbias + h * NTOK * NTOK;

    // ---- load + RN-round to tf32: q (scaled), k, vT ----
    for (int i = t; i < 3 * 512; i += 256) {
        int which = i >> 9;
        int rem   = i & 511;
        int r     = rem >> 3;
        int f     = rem & 7;
        float4 v4 = *(const float4*)(base + (size_t)r * QKV_N + which * CDIM + h * HD + f * 4);
        if (which == 0) {
            float4 o = { rtf(v4.x * SCALE), rtf(v4.y * SCALE),
                         rtf(v4.z * SCALE), rtf(v4.w * SCALE) };
            *(float4*)&sb[O_Q + r * AP + f * 4] = o;
        } else if (which == 1) {
            float4 o = { rtf(v4.x), rtf(v4.y), rtf(v4.z), rtf(v4.w) };
            *(float4*)&sb[O_K + r * AP + f * 4] = o;
        } else {
            sb[O_V + (f * 4 + 0) * SP + r] = rtf(v4.x);
            sb[O_V + (f * 4 + 1) * SP + r] = rtf(v4.y);
            sb[O_V + (f * 4 + 2) * SP + r] = rtf(v4.z);
            sb[O_V + (f * 4 + 3) * SP + r] = rtf(v4.w);
        }
    }
    __syncthreads();

    // ---- QK^T via mma: scores + bias -> sc ----
    {
        const uint32_t aoffQ = smb + (uint32_t)(O_Q + (wm * 16 + lsel * 8 + lrow8) * AP + lhalf * 4) * 4;
        const uint32_t boffK = smb + (uint32_t)(O_K + (wn * 32 + lhalf * 8 + lrow8) * AP + lsel * 4) * 4;
        float acc[4][4];
#pragma unroll
        for (int ni = 0; ni < 4; ni++)
#pragma unroll
            for (int j = 0; j < 4; j++) acc[ni][j] = 0.f;

#pragma unroll
        for (int ks = 0; ks < 4; ks++) {
            const uint32_t kb = (uint32_t)(ks * 8) * 4;
            uint32_t qf[4], bf[4][2];
            ldsm4(qf, aoffQ + kb);
            {
                uint32_t r[4];
                ldsm4(r, boffK + kb);
                bf[0][0] = r[0]; bf[0][1] = r[1]; bf[1][0] = r[2]; bf[1][1] = r[3];
                ldsm4(r, boffK + (uint32_t)(16 * AP) * 4 + kb);
                bf[2][0] = r[0]; bf[2][1] = r[1]; bf[3][0] = r[2]; bf[3][1] = r[3];
            }
#pragma unroll
            for (int ni = 0; ni < 4; ni++)
                mma8(acc[ni], qf, bf[ni]);
        }
#pragma unroll
        for (int ni = 0; ni < 4; ni++) {
            const int col = wn * 32 + ni * 8 + 2 * tg;
            const int r0 = wm * 16 + g;
            float2 b0 = *(const float2*)(biash + r0 * NTOK + col);
            float2 b1 = *(const float2*)(biash + (r0 + 8) * NTOK + col);
            *(float2*)&sb[O_S + r0 * SP + col]       = make_float2(acc[ni][0] + b0.x, acc[ni][1] + b0.y);
            *(float2*)&sb[O_S + (r0 + 8) * SP + col] = make_float2(acc[ni][2] + b1.x, acc[ni][3] + b1.y);
        }
    }
    __syncthreads();

    // ---- softmax: 4 threads/row; emit RN-rounded unnormalized p, 1/sum ----
    {
        const int r   = t >> 2;
        const int seg = (t & 3) * 16;
        float* SC = &sb[O_S + r * SP];
        float4 v0 = *(const float4*)&SC[seg];
        float4 v1 = *(const float4*)&SC[seg + 4];
        float4 v2 = *(const float4*)&SC[seg + 8];
        float4 v3 = *(const float4*)&SC[seg + 12];
        float mx = fmaxf(fmaxf(fmaxf(v0.x, v0.y), fmaxf(v0.z, v0.w)),
                   fmaxf(fmaxf(fmaxf(v1.x, v1.y), fmaxf(v1.z, v1.w)),
                   fmaxf(fmaxf(fmaxf(v2.x, v2.y), fmaxf(v2.z, v2.w)),
                         fmaxf(fmaxf(v3.x, v3.y), fmaxf(v3.z, v3.w)))));
        mx = fmaxf(mx, __shfl_xor_sync(0xffffffffu, mx, 1, 4));
        mx = fmaxf(mx, __shfl_xor_sync(0xffffffffu, mx, 2, 4));

        v0.x = fexp(v0.x - mx); v0.y = fexp(v0.y - mx);
        v0.z = fexp(v0.z - mx); v0.w = fexp(v0.w - mx);
        v1.x = fexp(v1.x - mx); v1.y = fexp(v1.y - mx);
        v1.z = fexp(v1.z - mx); v1.w = fexp(v1.w - mx);
        v2.x = fexp(v2.x - mx); v2.y = fexp(v2.y - mx);
        v2.z = fexp(v2.z - mx); v2.w = fexp(v2.w - mx);
        v3.x = fexp(v3.x - mx); v3.y = fexp(v3.y - mx);
        v3.z = fexp(v3.z - mx); v3.w = fexp(v3.w - mx);

        float sum = (v0.x + v0.y + v0.z + v0.w) + (v1.x + v1.y + v1.z + v1.w)
                  + (v2.x + v2.y + v2.z + v2.w) + (v3.x + v3.y + v3.z + v3.w);
        sum += __shfl_xor_sync(0xffffffffu, sum, 1, 4);
        sum += __shfl_xor_sync(0xffffffffu, sum, 2, 4);

        float4 o;
        o = make_float4(rtf(v0.x), rtf(v0.y), rtf(v0.z), rtf(v0.w)); *(float4*)&SC[seg]      = o;
        o = make_float4(rtf(v1.x), rtf(v1.y), rtf(v1.z), rtf(v1.w)); *(float4*)&SC[seg + 4]  = o;
        o = make_float4(rtf(v2.x), rtf(v2.y), rtf(v2.z), rtf(v2.w)); *(float4*)&SC[seg + 8]  = o;
        o = make_float4(rtf(v3.x), rtf(v3.y), rtf(v3.z), rtf(v3.w)); *(float4*)&SC[seg + 12] = o;
        if ((t & 3) == 0) sb[O_I + r] = 1.f / sum;
    }
    __syncthreads();

    // ---- P*V via mma: out rows wm*16+g(+8), d-cols wn*16.. ----
    {
        const uint32_t aoffP = smb + (uint32_t)(O_S + (wm * 16 + lsel * 8 + lrow8) * SP + lhalf * 4) * 4;
        const uint32_t boffV = smb + (uint32_t)(O_V + (wn * 16 + lhalf * 8 + lrow8) * SP + lsel * 4) * 4;
        float oacc[2][4];
#pragma unroll
        for (int ni = 0; ni < 2; ni++)
#pragma unroll
            for (int j = 0; j < 4; j++) oacc[ni][j] = 0.f;

#pragma unroll
        for (int ks = 0; ks < 8; ks++) {
            const uint32_t kb = (uint32_t)(ks * 8) * 4;
            uint32_t pf[4], vf[2][2];
            ldsm4(pf, aoffP + kb);
            {
                uint32_t r[4];
                ldsm4(r, boffV + kb);
                vf[0][0] = r[0]; vf[0][1] = r[1]; vf[1][0] = r[2]; vf[1][1] = r[3];
            }
#pragma unroll
            for (int ni = 0; ni < 2; ni++)
                mma8(oacc[ni], pf, vf[ni]);
        }
        const int r0 = wm * 16 + g;
        const float i0 = sb[O_I + r0];
        const float i1 = sb[O_I + r0 + 8];
#pragma unroll
        for (int ni = 0; ni < 2; ni++) {
            const int dcol = wn * 16 + ni * 8 + 2 * tg;
            float* op0 = out + (size_t)(b * NTOK + r0) * CDIM + h * HD + dcol;
            float* op1 = out + (size_t)(b * NTOK + r0 + 8) * CDIM + h * HD + dcol;
            *(float2*)op0 = make_float2(rtf(oacc[ni][0] * i0), rtf(oacc[ni][1] * i0));
            *(float2*)op1 = make_float2(rtf(oacc[ni][2] * i1), rtf(oacc[ni][3] * i1));
        }
    }
}

// ---------------------------------------------------------------------------
// Launch
// ---------------------------------------------------------------------------
extern "C" void kernel_launch(void* const* d_in, const int* in_sizes, int n_in,
                              void* d_out, int out_size)
{
    const float* x       = (const float*)d_in[0];
    const float* qkv_w   = (const float*)d_in[1];
    const float* qkv_b   = (const float*)d_in[2];
    const float* proj_w  = (const float*)d_in[3];
    const float* proj_b  = (const float*)d_in[4];
    const float* table   = (const float*)d_in[5];
    const int*   rpi     = (const int*)  d_in[6];
    float*       out     = (float*)d_out;

    float *qkv_s, *att_s, *wr_s, *bias_s;
    cudaGetSymbolAddress((void**)&qkv_s,  g_qkv);
    cudaGetSymbolAddress((void**)&att_s,  g_att);
    cudaGetSymbolAddress((void**)&wr_s,   g_wr);
    cudaGetSymbolAddress((void**)&bias_s, g_bias);
    float* wqkv_r  = wr_s;
    float* wproj_r = wr_s + QKV_N * CDIM;

    cudaFuncSetAttribute(gemm_mma_kernel<true>,
                         cudaFuncAttributeMaxDynamicSharedMemorySize, SMEM_DYN);
    cudaFuncSetAttribute(gemm_mma_kernel<false>,
                         cudaFuncAttributeMaxDynamicSharedMemorySize, SMEM_DYN);

    // 0) Precompute bias matrices + RN-round weights (tiny)
    bias_kernel<<<dim3(16, NH), 256>>>(table, rpi, bias_s);
    {
        int n4w1 = QKV_N * CDIM / 4;
        round_tf32_kernel<<<(n4w1 + 255) / 256, 256>>>((const float4*)qkv_w, (float4*)wqkv_r, n4w1);
        int n4w2 = CDIM * CDIM / 4;
        round_tf32_kernel<<<(n4w2 + 255) / 256, 256>>>((const float4*)proj_w, (float4*)wproj_r, n4w2);
    }

    // 1) QKV projection: A = raw x, rounded in-register (CVT_A=true)
    gemm_mma_kernel<true><<<dim3(QKV_N / BN, MROWS / BM), 256, SMEM_DYN>>>(
        x, wqkv_r, qkv_b, qkv_s, QKV_N);

    // 2) Window attention (tensor cores, 1-term RN-tf32)
    attn_kernel<<<dim3(B_NW, NH), 256>>>(qkv_s, bias_s, att_s);

    // 3) Output projection: A pre-rounded by attention (CVT_A=false)
    gemm_mma_kernel<false><<<dim3(CDIM / BN, MROWS / BM), 256, SMEM_DYN>>>(
        att_s, wproj_r, proj_b, out, CDIM);
}